// round 1
// baseline (speedup 1.0000x reference)
#include <cuda_runtime.h>
#include <math.h>

#define BATCH 32
#define NTOK  1024
#define CDIM  4096
#define HDIM  2048
#define DDIM  64
#define TTOT  (BATCH*NTOK)   /* 32768 tokens */

// ---------------- scratch (device globals; no allocation) ----------------
__device__ float g_ww1[CDIM*DDIM];          // ln_w[c]*w1[c,d]            (1 MB)
__device__ float g_csp[16][2][DDIM];        // column-sum partials
__device__ float g_cs[4][DDIM];             // 0:colsum_lo 1:cb_lo 2:colsum_hi 3:cb_hi
__device__ float g_S[(size_t)TTOT*DDIM];    // lower-half GEMM result     (8 MB)
__device__ float g_s1[TTOT];                // lower-half sum x
__device__ float g_s2[TTOT];                // lower-half sum x^2
__device__ float g_mu[TTOT];
__device__ float g_r[TTOT];
__device__ float g_Ap[(size_t)BATCH*64*HDIM]; // deterministic A partials (16 MB)
__device__ float g_A[BATCH*HDIM];
__device__ float g_gf[BATCH*DDIM];          // g + cb_lo + b1 folded

// ---------------- k_prep: ww1 = ln_w * w1 ----------------
__global__ void k_prep(const float* __restrict__ ln_w, const float* __restrict__ w1) {
    for (int i = blockIdx.x*blockDim.x + threadIdx.x; i < CDIM*DDIM; i += gridDim.x*blockDim.x)
        g_ww1[i] = ln_w[i >> 6] * w1[i];
}

// ---------------- k_cs: column sums of ln_w*w1 and ln_b*w1, per half ----------------
__global__ void k_cs(const float* __restrict__ ln_w, const float* __restrict__ ln_b,
                     const float* __restrict__ w1) {
    __shared__ float red[4][2][DDIM];
    int d = threadIdx.x & 63, s = threadIdx.x >> 6;
    int c0 = (blockIdx.x*4 + s) * 64;           // blocks 0-7 -> lower half, 8-15 -> upper
    float a0 = 0.f, a1 = 0.f;
    for (int cc = 0; cc < 64; cc++) {
        int c = c0 + cc;
        float wv = w1[c*DDIM + d];
        a0 += ln_w[c]*wv;
        a1 += ln_b[c]*wv;
    }
    red[s][0][d] = a0; red[s][1][d] = a1;
    __syncthreads();
    if (threadIdx.x < 128) {
        int which = threadIdx.x >> 6, dd = threadIdx.x & 63;
        g_csp[blockIdx.x][which][dd] =
            red[0][which][dd] + red[1][which][dd] + red[2][which][dd] + red[3][which][dd];
    }
}

__global__ void k_red(void) {
    int o = threadIdx.x >> 6, d = threadIdx.x & 63;
    int base = (o >= 2) ? 8 : 0;
    int which = o & 1;
    float s = 0.f;
    #pragma unroll
    for (int bi = 0; bi < 8; bi++) s += g_csp[base + bi][which][d];
    g_cs[o][d] = s;
}

// ---------------- k_main: S[t,d] = sum_{c<2048} x[t,c]*ww1[c,d]  + lower moments ----------------
__global__ void __launch_bounds__(256) k_main(const float* __restrict__ x) {
    __shared__ __align__(16) float xs[64][68];   // [token][k], pitch keeps float4 stores aligned
    __shared__ __align__(16) float ws[64][64];   // [k][d]
    __shared__ float red[2][4][64];
    int tid = threadIdx.x;
    int t0  = blockIdx.x * 64;
    int ty = tid >> 4, tx = tid & 15;            // 16x16 thread grid; 4 tok x 4 d each
    int ts = tid & 63, sl = tid >> 6;            // stats assignment
    float acc[4][4];
    #pragma unroll
    for (int i = 0; i < 4; i++)
        #pragma unroll
        for (int j = 0; j < 4; j++) acc[i][j] = 0.f;
    float s1 = 0.f, s2 = 0.f;

    for (int cc = 0; cc < HDIM; cc += 64) {
        #pragma unroll
        for (int l = 0; l < 4; l++) {
            int idx = tid + l*256;
            int r = idx >> 4, q = idx & 15;
            *(float4*)&xs[r][4*q] = *(const float4*)(x + (size_t)(t0 + r)*CDIM + cc + 4*q);
            *(float4*)&ws[r][4*q] = *(const float4*)(g_ww1 + (size_t)(cc + r)*DDIM + 4*q);
        }
        __syncthreads();
        // lower-half moments (each thread owns token ts, k-slice sl*16..+16)
        #pragma unroll
        for (int kk = 0; kk < 16; kk++) {
            float v = xs[ts][sl*16 + kk];
            s1 += v; s2 += v*v;
        }
        // GEMM
        #pragma unroll 8
        for (int k = 0; k < 64; k++) {
            float4 b4 = *(const float4*)&ws[k][4*tx];
            float a0 = xs[4*ty + 0][k];
            float a1 = xs[4*ty + 1][k];
            float a2 = xs[4*ty + 2][k];
            float a3 = xs[4*ty + 3][k];
            acc[0][0] += a0*b4.x; acc[0][1] += a0*b4.y; acc[0][2] += a0*b4.z; acc[0][3] += a0*b4.w;
            acc[1][0] += a1*b4.x; acc[1][1] += a1*b4.y; acc[1][2] += a1*b4.z; acc[1][3] += a1*b4.w;
            acc[2][0] += a2*b4.x; acc[2][1] += a2*b4.y; acc[2][2] += a2*b4.z; acc[2][3] += a2*b4.w;
            acc[3][0] += a3*b4.x; acc[3][1] += a3*b4.y; acc[3][2] += a3*b4.z; acc[3][3] += a3*b4.w;
        }
        __syncthreads();
    }
    #pragma unroll
    for (int i = 0; i < 4; i++) {
        float4 v = make_float4(acc[i][0], acc[i][1], acc[i][2], acc[i][3]);
        *(float4*)(g_S + (size_t)(t0 + 4*ty + i)*DDIM + 4*tx) = v;
    }
    red[0][sl][ts] = s1; red[1][sl][ts] = s2;
    __syncthreads();
    if (tid < 64) {
        g_s1[t0 + tid] = red[0][0][tid] + red[0][1][tid] + red[0][2][tid] + red[0][3][tid];
        g_s2[t0 + tid] = red[1][0][tid] + red[1][1][tid] + red[1][2][tid] + red[1][3][tid];
    }
}

// ---------------- k_upper: finalize mu,r; A partials over upper half ----------------
__global__ void __launch_bounds__(256) k_upper(const float* __restrict__ x) {
    extern __shared__ float xu[];               // [16][2048] = 128 KB
    __shared__ float rr[16];
    int tid = threadIdx.x;
    int t0 = blockIdx.x * 16;
    int b  = t0 >> 10;

    const float4* X4 = (const float4*)x;
    float4* xu4 = (float4*)xu;
    #pragma unroll
    for (int l = 0; l < 32; l++) {
        int idx = tid + l*256;                  // 0..8191 float4s
        int r = idx >> 9, q = idx & 511;
        xu4[r*512 + q] = X4[(size_t)(t0 + r)*1024 + 512 + q];   // upper half of row
    }
    __syncthreads();

    int w = tid >> 5, lane = tid & 31;
    #pragma unroll
    for (int rep = 0; rep < 2; rep++) {
        int tok = w*2 + rep;
        float s1 = 0.f, s2 = 0.f;
        #pragma unroll 8
        for (int k = 0; k < 64; k++) {
            float v = xu[tok*2048 + lane + 32*k];
            s1 += v; s2 += v*v;
        }
        #pragma unroll
        for (int o = 16; o > 0; o >>= 1) {
            s1 += __shfl_down_sync(0xffffffffu, s1, o);
            s2 += __shfl_down_sync(0xffffffffu, s2, o);
        }
        if (lane == 0) {
            int t = t0 + tok;
            float S1 = g_s1[t] + s1;
            float S2 = g_s2[t] + s2;
            float mu  = S1 * (1.0f/4096.0f);
            float var = S2 * (1.0f/4096.0f) - mu*mu;
            float rv  = rsqrtf(var + 1e-5f);
            g_mu[t] = mu; g_r[t] = rv; rr[tok] = rv;
        }
    }
    __syncthreads();

    int cib = blockIdx.x & 63;                  // CTA index within batch (deterministic slot)
    float* Ap = g_Ap + (size_t)(b*64 + cib)*HDIM;
    #pragma unroll
    for (int m = 0; m < 8; m++) {
        int j = tid + m*256;
        float acc = 0.f;
        #pragma unroll
        for (int t = 0; t < 16; t++) acc += xu[t*2048 + j] * rr[t];
        Ap[j] = acc;
    }
}

// ---------------- k_redA: reduce 64 partials -> A (includes 1/N) ----------------
__global__ void k_redA(void) {
    int i = blockIdx.x*blockDim.x + threadIdx.x;     // 65536
    int b = i >> 11, j = i & 2047;
    float s = 0.f;
    #pragma unroll 8
    for (int p = 0; p < 64; p++) s += g_Ap[(size_t)(b*64 + p)*HDIM + j];
    g_A[i] = s * (1.0f/1024.0f);
}

// ---------------- k_g: per-batch global contribution (+ fold cb_lo + b1) ----------------
__global__ void k_g(const float* __restrict__ b1) {
    __shared__ float red[4][64];
    __shared__ float mred[256];
    int b = blockIdx.x, tid = threadIdx.x;
    float m = 0.f;
    #pragma unroll
    for (int k = 0; k < 4; k++) {
        int t = b*1024 + tid + k*256;
        m += g_mu[t] * g_r[t];
    }
    mred[tid] = m;
    __syncthreads();
    for (int o = 128; o > 0; o >>= 1) {
        if (tid < o) mred[tid] += mred[tid + o];
        __syncthreads();
    }
    float m_b = mred[0] * (1.0f/1024.0f);

    int d = tid & 63, s = tid >> 6;
    float acc = 0.f;
    const float* A = g_A + b*HDIM;
    for (int jj = 0; jj < 512; jj++) {
        int j = s*512 + jj;
        acc += g_ww1[(size_t)(HDIM + j)*DDIM + d] * A[j];
    }
    red[s][d] = acc;
    __syncthreads();
    if (tid < 64) {
        float g = red[0][tid] + red[1][tid] + red[2][tid] + red[3][tid];
        g_gf[b*DDIM + tid] = g - m_b*g_cs[2][tid] + g_cs[3][tid] + g_cs[1][tid] + b1[tid];
    }
}

// ---------------- k_epi: gate decision + out = x * keep ----------------
__global__ void __launch_bounds__(256) k_epi(const float* __restrict__ x,
                                             const float* __restrict__ gum,
                                             const float* __restrict__ w2,
                                             const float* __restrict__ b2,
                                             float* __restrict__ out) {
    __shared__ float keep[8];
    int tid = threadIdx.x, w = tid >> 5, lane = tid & 31;
    int t0 = blockIdx.x * 8;
    int t  = t0 + w;
    int b  = t >> 10;
    float mu = g_mu[t], rv = g_r[t];
    float l0 = 0.f, l1 = 0.f;
    #pragma unroll
    for (int p = 0; p < 2; p++) {
        int d = lane + 32*p;
        float sv = g_S[(size_t)t*DDIM + d];
        float h  = rv*(sv - mu*g_cs[0][d]) + g_gf[b*DDIM + d];
        float ge = 0.5f*h*(1.0f + erff(h*0.70710678118654752f));   // exact gelu
        l0 += ge * w2[d*2 + 0];
        l1 += ge * w2[d*2 + 1];
    }
    #pragma unroll
    for (int o = 16; o > 0; o >>= 1) {
        l0 += __shfl_down_sync(0xffffffffu, l0, o);
        l1 += __shfl_down_sync(0xffffffffu, l1, o);
    }
    if (lane == 0) {
        l0 += b2[0] + gum[t*2 + 0];
        l1 += b2[1] + gum[t*2 + 1];
        keep[w] = (l0 >= l1) ? 1.0f : 0.0f;    // argmax ties -> index 0 wins
    }
    __syncthreads();
    const float4* X4 = (const float4*)x;
    float4* O4 = (float4*)out;
    #pragma unroll
    for (int l = 0; l < 32; l++) {
        int idx = tid + l*256;                 // 8 rows x 1024 float4
        int r = idx >> 10, q = idx & 1023;
        float kv = keep[r];
        float4 v = X4[(size_t)(t0 + r)*1024 + q];
        v.x *= kv; v.y *= kv; v.z *= kv; v.w *= kv;
        O4[(size_t)(t0 + r)*1024 + q] = v;
    }
}

// ---------------- launch ----------------
extern "C" void kernel_launch(void* const* d_in, const int* in_sizes, int n_in,
                              void* d_out, int out_size) {
    const float* x    = (const float*)d_in[0];
    const float* gum  = (const float*)d_in[1];
    const float* ln_w = (const float*)d_in[2];
    const float* ln_b = (const float*)d_in[3];
    const float* w1   = (const float*)d_in[4];
    const float* b1   = (const float*)d_in[5];
    const float* w2   = (const float*)d_in[6];
    const float* b2   = (const float*)d_in[7];
    float* out = (float*)d_out;

    cudaFuncSetAttribute(k_upper, cudaFuncAttributeMaxDynamicSharedMemorySize, 16*2048*4);

    k_prep<<<256, 256>>>(ln_w, w1);
    k_cs  <<<16, 256>>>(ln_w, ln_b, w1);
    k_red <<<1, 256>>>();
    k_main<<<TTOT/64, 256>>>(x);
    k_upper<<<TTOT/16, 256, 16*2048*4>>>(x);
    k_redA<<<256, 256>>>();
    k_g   <<<BATCH, 256>>>(b1);
    k_epi <<<TTOT/8, 256>>>(x, gum, w2, b2, out);
}